// round 1
// baseline (speedup 1.0000x reference)
#include <cuda_runtime.h>
#include <cuda_bf16.h>

// Problem constants (Qwen3MoeSparseMoeBlock_2413771621126)
#define T_TOK   1024      // 2*512 tokens
#define HID     2048
#define NEXP    16
#define TOPK    4
#define INTER   768       // moe_intermediate_size
#define INTER2  1536      // 2*INTER

// ---------------- device scratch (static; allocation-free) ----------------
__device__ int   g_cnt[NEXP];
__device__ int   g_tok[NEXP * T_TOK];
__device__ float g_wt [NEXP * T_TOK];
// h buffer: [expert][token-slot][INTER], slot index = e*T_TOK + m (m < cnt[e])
__device__ float g_h  [(size_t)NEXP * T_TOK * INTER];   // ~50.3 MB

// ---------------- phase 0: zero out + counters ----------------
__global__ void zero_kernel(float* __restrict__ out, int n) {
    int i = blockIdx.x * blockDim.x + threadIdx.x;
    if (i < n) out[i] = 0.0f;
    if (blockIdx.x == 0 && threadIdx.x < NEXP) g_cnt[threadIdx.x] = 0;
}

// ---------------- phase 1: router (one block of 128 threads per token) ----
__global__ void __launch_bounds__(128) router_kernel(
    const float* __restrict__ x,          // [T, H]
    const float* __restrict__ rw)         // [E, H]
{
    int t   = blockIdx.x;
    int tid = threadIdx.x;

    float acc[NEXP];
#pragma unroll
    for (int e = 0; e < NEXP; e++) acc[e] = 0.0f;

    const float* xr = x + (size_t)t * HID;
    for (int k = tid; k < HID; k += 128) {
        float xv = xr[k];
#pragma unroll
        for (int e = 0; e < NEXP; e++)
            acc[e] += xv * rw[e * HID + k];
    }

    // warp reduce
#pragma unroll
    for (int e = 0; e < NEXP; e++) {
#pragma unroll
        for (int off = 16; off > 0; off >>= 1)
            acc[e] += __shfl_down_sync(0xFFFFFFFFu, acc[e], off);
    }

    __shared__ float spart[4][NEXP];
    int warp = tid >> 5, lane = tid & 31;
    if (lane == 0) {
#pragma unroll
        for (int e = 0; e < NEXP; e++) spart[warp][e] = acc[e];
    }
    __syncthreads();

    if (tid == 0) {
        float logit[NEXP];
#pragma unroll
        for (int e = 0; e < NEXP; e++)
            logit[e] = spart[0][e] + spart[1][e] + spart[2][e] + spart[3][e];

        // top-4 (lower index wins ties, matching lax.top_k)
        int   idx[TOPK];
        float val[TOPK];
        bool  used[NEXP];
#pragma unroll
        for (int e = 0; e < NEXP; e++) used[e] = false;
#pragma unroll
        for (int k = 0; k < TOPK; k++) {
            float best = -1e30f; int bi = 0;
            for (int e = 0; e < NEXP; e++) {
                if (!used[e] && logit[e] > best) { best = logit[e]; bi = e; }
            }
            used[bi] = true; idx[k] = bi; val[k] = best;
        }
        // normalized softmax over the selected 4 (== renormalized top-k probs)
        float mx = val[0];
        float s = 0.0f;
        float ev[TOPK];
#pragma unroll
        for (int k = 0; k < TOPK; k++) { ev[k] = expf(val[k] - mx); s += ev[k]; }
        float inv = 1.0f / s;
#pragma unroll
        for (int k = 0; k < TOPK; k++) {
            int e   = idx[k];
            int pos = atomicAdd(&g_cnt[e], 1);
            g_tok[e * T_TOK + pos] = t;
            g_wt [e * T_TOK + pos] = ev[k] * inv;
        }
    }
}

// ---------------- phase 2: gathered GEMM gate_up + SiLU*up*wt -> g_h -------
// grid: (INTER/64, T_TOK/64, NEXP), block 256 threads, 64x64 tile, 4x4/thread
#define BT 64
#define KT 16
__global__ void __launch_bounds__(256) gateup_kernel(
    const float* __restrict__ x,          // [T, H]
    const float* __restrict__ gup)        // [E, H, 2I]
{
    int e   = blockIdx.z;
    int cnt = g_cnt[e];
    int mbase = blockIdx.y * BT;
    if (mbase >= cnt) return;
    int nbase = blockIdx.x * BT;          // gate column base in [0, INTER)

    __shared__ float As[KT][BT + 1];
    __shared__ float Bg[KT][BT];
    __shared__ float Bu[KT][BT];

    int tid = threadIdx.x;
    int tx  = tid & 15;                    // col group
    int ty  = tid >> 4;                    // row group

    // A-load mapping: each thread loads one float4 of x
    int am = tid >> 2;                     // 0..63  (tile row)
    int ak = (tid & 3) * 4;                // 0,4,8,12
    int gm = mbase + am;
    int tok = (gm < cnt) ? g_tok[e * T_TOK + gm] : 0;
    bool avalid = (gm < cnt);

    // B-load mapping: row = tid>>4 (0..15), col4 = (tid&15)*4
    int bk = tid >> 4;
    int bn = (tid & 15) * 4;

    float accG[4][4], accU[4][4];
#pragma unroll
    for (int i = 0; i < 4; i++)
#pragma unroll
        for (int j = 0; j < 4; j++) { accG[i][j] = 0.0f; accU[i][j] = 0.0f; }

    for (int k0 = 0; k0 < HID; k0 += KT) {
        float4 av = make_float4(0.f, 0.f, 0.f, 0.f);
        if (avalid)
            av = *reinterpret_cast<const float4*>(&x[(size_t)tok * HID + k0 + ak]);
        As[ak + 0][am] = av.x;
        As[ak + 1][am] = av.y;
        As[ak + 2][am] = av.z;
        As[ak + 3][am] = av.w;

        const float* bp = &gup[((size_t)e * HID + k0 + bk) * INTER2 + nbase + bn];
        float4 bg = *reinterpret_cast<const float4*>(bp);
        float4 bu = *reinterpret_cast<const float4*>(bp + INTER);
        *reinterpret_cast<float4*>(&Bg[bk][bn]) = bg;
        *reinterpret_cast<float4*>(&Bu[bk][bn]) = bu;
        __syncthreads();

#pragma unroll
        for (int kk = 0; kk < KT; kk++) {
            float a0 = As[kk][ty * 4 + 0];
            float a1 = As[kk][ty * 4 + 1];
            float a2 = As[kk][ty * 4 + 2];
            float a3 = As[kk][ty * 4 + 3];
            float4 g = *reinterpret_cast<const float4*>(&Bg[kk][tx * 4]);
            float4 u = *reinterpret_cast<const float4*>(&Bu[kk][tx * 4]);

            accG[0][0] += a0 * g.x; accG[0][1] += a0 * g.y; accG[0][2] += a0 * g.z; accG[0][3] += a0 * g.w;
            accG[1][0] += a1 * g.x; accG[1][1] += a1 * g.y; accG[1][2] += a1 * g.z; accG[1][3] += a1 * g.w;
            accG[2][0] += a2 * g.x; accG[2][1] += a2 * g.y; accG[2][2] += a2 * g.z; accG[2][3] += a2 * g.w;
            accG[3][0] += a3 * g.x; accG[3][1] += a3 * g.y; accG[3][2] += a3 * g.z; accG[3][3] += a3 * g.w;

            accU[0][0] += a0 * u.x; accU[0][1] += a0 * u.y; accU[0][2] += a0 * u.z; accU[0][3] += a0 * u.w;
            accU[1][0] += a1 * u.x; accU[1][1] += a1 * u.y; accU[1][2] += a1 * u.z; accU[1][3] += a1 * u.w;
            accU[2][0] += a2 * u.x; accU[2][1] += a2 * u.y; accU[2][2] += a2 * u.z; accU[2][3] += a2 * u.w;
            accU[3][0] += a3 * u.x; accU[3][1] += a3 * u.y; accU[3][2] += a3 * u.z; accU[3][3] += a3 * u.w;
        }
        __syncthreads();
    }

    // epilogue: h = silu(gate) * up * combine_wt  -> g_h
#pragma unroll
    for (int i = 0; i < 4; i++) {
        int m = mbase + ty * 4 + i;
        if (m >= cnt) continue;
        float w = g_wt[e * T_TOK + m];
        float* hp = &g_h[((size_t)e * T_TOK + m) * INTER + nbase + tx * 4];
        float4 hv;
        float gv, uv;
        gv = accG[i][0]; uv = accU[i][0]; hv.x = (gv / (1.0f + expf(-gv))) * uv * w;
        gv = accG[i][1]; uv = accU[i][1]; hv.y = (gv / (1.0f + expf(-gv))) * uv * w;
        gv = accG[i][2]; uv = accU[i][2]; hv.z = (gv / (1.0f + expf(-gv))) * uv * w;
        gv = accG[i][3]; uv = accU[i][3]; hv.w = (gv / (1.0f + expf(-gv))) * uv * w;
        *reinterpret_cast<float4*>(hp) = hv;
    }
}

// ---------------- phase 3: down-proj GEMM, atomic scatter into out --------
// grid: (HID/64, T_TOK/64, NEXP)
__global__ void __launch_bounds__(256) down_kernel(
    const float* __restrict__ down,       // [E, I, H]
    float* __restrict__ out)              // [T, H]
{
    int e   = blockIdx.z;
    int cnt = g_cnt[e];
    int mbase = blockIdx.y * BT;
    if (mbase >= cnt) return;
    int nbase = blockIdx.x * BT;

    __shared__ float As[KT][BT + 1];
    __shared__ float Bs[KT][BT];

    int tid = threadIdx.x;
    int tx  = tid & 15;
    int ty  = tid >> 4;

    int am = tid >> 2;
    int ak = (tid & 3) * 4;
    int gm = mbase + am;
    bool avalid = (gm < cnt);
    const float* arow = &g_h[((size_t)e * T_TOK + gm) * INTER];

    int bk = tid >> 4;
    int bn = (tid & 15) * 4;

    float acc[4][4];
#pragma unroll
    for (int i = 0; i < 4; i++)
#pragma unroll
        for (int j = 0; j < 4; j++) acc[i][j] = 0.0f;

    for (int k0 = 0; k0 < INTER; k0 += KT) {
        float4 av = make_float4(0.f, 0.f, 0.f, 0.f);
        if (avalid)
            av = *reinterpret_cast<const float4*>(&arow[k0 + ak]);
        As[ak + 0][am] = av.x;
        As[ak + 1][am] = av.y;
        As[ak + 2][am] = av.z;
        As[ak + 3][am] = av.w;

        float4 bv = *reinterpret_cast<const float4*>(
            &down[((size_t)e * INTER + k0 + bk) * HID + nbase + bn]);
        *reinterpret_cast<float4*>(&Bs[bk][bn]) = bv;
        __syncthreads();

#pragma unroll
        for (int kk = 0; kk < KT; kk++) {
            float a0 = As[kk][ty * 4 + 0];
            float a1 = As[kk][ty * 4 + 1];
            float a2 = As[kk][ty * 4 + 2];
            float a3 = As[kk][ty * 4 + 3];
            float4 b = *reinterpret_cast<const float4*>(&Bs[kk][tx * 4]);

            acc[0][0] += a0 * b.x; acc[0][1] += a0 * b.y; acc[0][2] += a0 * b.z; acc[0][3] += a0 * b.w;
            acc[1][0] += a1 * b.x; acc[1][1] += a1 * b.y; acc[1][2] += a1 * b.z; acc[1][3] += a1 * b.w;
            acc[2][0] += a2 * b.x; acc[2][1] += a2 * b.y; acc[2][2] += a2 * b.z; acc[2][3] += a2 * b.w;
            acc[3][0] += a3 * b.x; acc[3][1] += a3 * b.y; acc[3][2] += a3 * b.z; acc[3][3] += a3 * b.w;
        }
        __syncthreads();
    }

#pragma unroll
    for (int i = 0; i < 4; i++) {
        int m = mbase + ty * 4 + i;
        if (m >= cnt) continue;
        int t = g_tok[e * T_TOK + m];
        float* op = &out[(size_t)t * HID + nbase + tx * 4];
#pragma unroll
        for (int j = 0; j < 4; j++)
            atomicAdd(op + j, acc[i][j]);
    }
}

// ---------------- launch ----------------
extern "C" void kernel_launch(void* const* d_in, const int* in_sizes, int n_in,
                              void* d_out, int out_size)
{
    const float* x    = (const float*)d_in[0];   // [2,512,2048]
    const float* rw   = (const float*)d_in[1];   // [16,2048]
    const float* gup  = (const float*)d_in[2];   // [16,2048,1536]
    const float* down = (const float*)d_in[3];   // [16,768,2048]
    float* out = (float*)d_out;                  // [2,512,2048]

    int n_out = T_TOK * HID;
    zero_kernel<<<(n_out + 511) / 512, 512>>>(out, n_out);

    router_kernel<<<T_TOK, 128>>>(x, rw);

    dim3 gridB(INTER / BT, T_TOK / BT, NEXP);   // (12, 16, 16)
    gateup_kernel<<<gridB, 256>>>(x, gup);

    dim3 gridC(HID / BT, T_TOK / BT, NEXP);     // (32, 16, 16)
    down_kernel<<<gridC, 256>>>(down, out);
}